// round 7
// baseline (speedup 1.0000x reference)
#include <cuda_runtime.h>
#include <math.h>

#define VOL    110592   // 48*48*48
#define HV     55296    // VOL/2
#define PLANE  2304     // 48*48
#define NVOX   221184   // B * VOL
#define TOTALE 884736   // B*C*VOL
#define INF9   1.0e9f
#define LUTN   6640
#define LOSSBLKS 432    // NVOX / 2 / 256

// Static scratch (no allocations allowed)
__device__ unsigned short g_bufS1[8 * VOL];  // pos^2 after W+H (ushort, clamped)
__device__ unsigned short g_bufS2[8 * VOL];  // pos^2 after W+H+D (ushort, clamped)
__device__ float  g_lut[LUTN];
__device__ int    g_flags[8];   // zero-init; reset by loss epilogue each replay
__device__ int    g_count;     // zero-init; reset by loss epilogue each replay
__device__ double g_partials[LOSSBLKS];

// ---------------------------------------------------------------------------
// Kernel A: one block per (m=b*4+c, d) plane, 192 threads. Self-detects
// target dtype, builds class line masks, exact W-EDT via clz/ffs, exact H
// min-plus. Stores W+H squared dists as ushort (clamp 65535). Block 0 also
// builds the sqrt LUT.
// ---------------------------------------------------------------------------
__global__ void __launch_bounds__(192) kA(const void* __restrict__ target) {
    __shared__ unsigned char lab[PLANE];
    __shared__ unsigned long long lmask[48];
    __shared__ float s[48][49];
    __shared__ int sbad;
    __shared__ int anyflag;

    const int tid = threadIdx.x;
    const int m = blockIdx.x / 48;         // b*4 + c
    const int d = blockIdx.x - m * 48;
    const int b = m >> 2;
    const int c = m & 3;

    if (tid < 48) lmask[tid] = 0ULL;
    if (tid == 0) { anyflag = 0; sbad = 0; }
    __syncthreads();

    // dtype detection from the first 512 bytes (in-bounds for both dtypes).
    if (tid < 64) {
        long long v = ((const long long*)target)[tid];
        if (v < 0 || v > 3) atomicOr(&sbad, 1);
    }
    __syncthreads();
    const bool is64 = (sbad == 0);

    const int vbase = b * VOL + d * PLANE;
    if (is64) {
        const long long* tp = (const long long*)target;
        for (int i = tid; i < PLANE; i += 192) lab[i] = (unsigned char)tp[vbase + i];
    } else {
        const int* tp = (const int*)target;
        for (int i = tid; i < PLANE; i += 192) lab[i] = (unsigned char)tp[vbase + i];
    }
    __syncthreads();

    // Per-line seed bitmasks.
    {
        int h = tid >> 2;
        int w0 = (tid & 3) * 12;
        unsigned long long bits = 0ULL;
        #pragma unroll
        for (int k = 0; k < 12; k++) {
            int w = w0 + k;
            unsigned long long isc =
                (unsigned long long)(lab[h * 48 + w] == (unsigned char)c);
            bits |= isc << w;
        }
        if (bits) { atomicOr(&lmask[h], bits); anyflag = 1; }
    }
    __syncthreads();
    if (tid == 0 && anyflag) atomicOr(&g_flags[m], 1);

    // Block 0 builds sqrt LUT (consumed two kernels later).
    if (blockIdx.x == 0) {
        for (int i = tid; i < LUTN; i += 192) g_lut[i] = sqrtf((float)i);
    }

    // Exact W distances via clz/ffs; fold +h^2 for the H pass.
    #pragma unroll
    for (int k = 0; k < 12; k++) {
        int i = tid + k * 192;
        int hh = i / 48;
        int ww = i - hh * 48;
        unsigned long long mm = lmask[hh];
        unsigned long long lowm = mm << (63 - ww);
        unsigned long long him  = mm >> ww;
        int dl = lowm ? __clzll(lowm) : 99;
        int dr = him ? (__ffsll(him) - 1) : 99;
        int dd = min(dl, dr);
        float v = (dd <= 47) ? (float)(dd * dd) : INF9;
        s[hh][ww] = v + (float)(hh * hh);
    }
    __syncthreads();

    // H min-plus: grp owns 12 outputs x; lane = w.
    const int grp = tid & 3;
    const int lane = tid >> 2;
    float acc[12], xv[12];
    #pragma unroll
    for (int k = 0; k < 12; k++) { acc[k] = 1.0e30f; xv[k] = (float)(grp * 12 + k); }

    #pragma unroll
    for (int jc = 0; jc < 4; jc++) {
        float sv[12];
        #pragma unroll
        for (int t = 0; t < 12; t++) sv[t] = s[jc * 12 + t][lane];
        #pragma unroll
        for (int t = 0; t < 12; t++) {
            const float cj = -2.0f * (float)(jc * 12 + t);
            #pragma unroll
            for (int k = 0; k < 12; k++)
                acc[k] = fminf(acc[k], fmaf(cj, xv[k], sv[t]));
        }
    }

    const int base = m * VOL + d * PLANE;
    #pragma unroll
    for (int k = 0; k < 12; k++) {
        int x = grp * 12 + k;
        float val = acc[k] + (float)(x * x);
        g_bufS1[base + x * 48 + lane] = (unsigned short)fminf(val, 65535.0f);
    }
}

// ---------------------------------------------------------------------------
// Kernel B: exact D min-plus. One block per (m, h) plane (d, w), 192 threads.
// ushort in -> ushort out (clamped; present-class values exact, <= 6627).
// ---------------------------------------------------------------------------
__global__ void __launch_bounds__(192) kB() {
    __shared__ float s[48][49];
    const int tid = threadIdx.x;
    const int m = blockIdx.x / 48;
    const int h = blockIdx.x - m * 48;
    const int base = m * VOL + h * 48;

    for (int i = tid; i < PLANE; i += 192) {
        int dd = i / 48;
        int w = i - dd * 48;
        s[dd][w] = (float)g_bufS1[base + dd * PLANE + w] + (float)(dd * dd);
    }
    __syncthreads();

    const int grp = tid & 3;
    const int lane = tid >> 2;
    float acc[12], xv[12];
    #pragma unroll
    for (int k = 0; k < 12; k++) { acc[k] = 1.0e30f; xv[k] = (float)(grp * 12 + k); }

    #pragma unroll
    for (int jc = 0; jc < 4; jc++) {
        float sv[12];
        #pragma unroll
        for (int t = 0; t < 12; t++) sv[t] = s[jc * 12 + t][lane];
        #pragma unroll
        for (int t = 0; t < 12; t++) {
            const float cj = -2.0f * (float)(jc * 12 + t);
            #pragma unroll
            for (int k = 0; k < 12; k++)
                acc[k] = fminf(acc[k], fmaf(cj, xv[k], sv[t]));
        }
    }

    #pragma unroll
    for (int k = 0; k < 12; k++) {
        int x = grp * 12 + k;
        float val = acc[k] + (float)(x * x);
        g_bufS2[base + x * PLANE + lane] = (unsigned short)fminf(val, 65535.0f);
    }
}

// ---------------------------------------------------------------------------
// Loss: 2 voxels/thread (float2 pred, ushort2 dist, front-batched MLP=8).
// q_c = LUT[pos2_c]; |sdf_c| = q_c + min_{c'!=c} q_{c'} (exact: one term 0,
// min commutes with sqrt). Branch-free flag multipliers. Deterministic
// double reduction; last block finishes + resets globals for next replay.
// ---------------------------------------------------------------------------
__global__ void __launch_bounds__(256) k_loss(const float* __restrict__ pred,
                                              float* __restrict__ out) {
    const int t = blockIdx.x * 256 + threadIdx.x;   // 0..110591
    const int b = t / HV;
    const int r = t - b * HV;
    const int base2 = b * 4 * HV + r;

    const float2*  p2 = (const float2*)pred;
    const ushort2* q2 = (const ushort2*)g_bufS2;

    float2  P[4];
    ushort2 Dv[4];
    #pragma unroll
    for (int c = 0; c < 4; c++) P[c] = __ldg(&p2[base2 + c * HV]);
    #pragma unroll
    for (int c = 0; c < 4; c++) Dv[c] = __ldg(&q2[base2 + c * HV]);

    float fl[4];
    #pragma unroll
    for (int c = 0; c < 4; c++) fl[c] = g_flags[b * 4 + c] ? 1.0f : 0.0f;

    double sum = 0.0;
    #pragma unroll
    for (int v = 0; v < 2; v++) {
        float p0 = v ? P[0].y : P[0].x;
        float p1 = v ? P[1].y : P[1].x;
        float p2v = v ? P[2].y : P[2].x;
        float p3 = v ? P[3].y : P[3].x;
        int i0 = v ? Dv[0].y : Dv[0].x;
        int i1 = v ? Dv[1].y : Dv[1].x;
        int i2 = v ? Dv[2].y : Dv[2].x;
        int i3 = v ? Dv[3].y : Dv[3].x;

        float q0 = (i0 < LUTN) ? __ldg(&g_lut[i0]) : sqrtf((float)i0);
        float q1 = (i1 < LUTN) ? __ldg(&g_lut[i1]) : sqrtf((float)i1);
        float q2c = (i2 < LUTN) ? __ldg(&g_lut[i2]) : sqrtf((float)i2);
        float q3 = (i3 < LUTN) ? __ldg(&g_lut[i3]) : sqrtf((float)i3);

        float mx = fmaxf(fmaxf(p0, p1), fmaxf(p2v, p3));
        float e0 = __expf(p0 - mx);
        float e1 = __expf(p1 - mx);
        float e2 = __expf(p2v - mx);
        float e3 = __expf(p3 - mx);
        float inv = __fdividef(1.0f, e0 + e1 + e2 + e3);

        float m01 = fminf(q0, q1), m23 = fminf(q2c, q3);
        float s0 = q0 + fminf(q1, m23);
        float s1 = q1 + fminf(q0, m23);
        float s2 = q2c + fminf(m01, q3);
        float s3 = q3 + fminf(m01, q2c);

        float local = fl[0] * e0 * s0 + fl[1] * e1 * s1
                    + fl[2] * e2 * s2 + fl[3] * e3 * s3;
        sum += (double)(local * inv);
    }

    __shared__ double sh[256];
    __shared__ int islast;
    sh[threadIdx.x] = sum;
    __syncthreads();
    #pragma unroll
    for (int st = 128; st > 0; st >>= 1) {
        if (threadIdx.x < st) sh[threadIdx.x] += sh[threadIdx.x + st];
        __syncthreads();
    }
    if (threadIdx.x == 0) {
        g_partials[blockIdx.x] = sh[0];
        __threadfence();
        int done = atomicAdd(&g_count, 1);
        islast = (done == gridDim.x - 1);
    }
    __syncthreads();

    if (islast) {
        int i2n = threadIdx.x + 256;
        double v = g_partials[threadIdx.x]
                 + ((i2n < LOSSBLKS) ? g_partials[i2n] : 0.0);
        sh[threadIdx.x] = v;
        __syncthreads();
        #pragma unroll
        for (int st = 128; st > 0; st >>= 1) {
            if (threadIdx.x < st) sh[threadIdx.x] += sh[threadIdx.x + st];
            __syncthreads();
        }
        if (threadIdx.x == 0) {
            out[0] = (float)(sh[0] / (double)TOTALE);
            g_count = 0;                    // reset for next graph replay
        }
        if (threadIdx.x < 8) g_flags[threadIdx.x] = 0;
    }
}

// ---------------------------------------------------------------------------
extern "C" void kernel_launch(void* const* d_in, const int* in_sizes, int n_in,
                              void* d_out, int out_size) {
    const float* pred   = (const float*)d_in[0];
    const void*  target = d_in[1];
    float* out = (float*)d_out;

    kA<<<8 * 48, 192>>>(target);        // init + W bit-scan + H min-plus
    kB<<<8 * 48, 192>>>();              // D min-plus
    k_loss<<<LOSSBLKS, 256>>>(pred, out);
}